// round 7
// baseline (speedup 1.0000x reference)
#include <cuda_runtime.h>
#include <cuda_fp16.h>
#include <cstdint>

// ============================================================================
// SAE forward on sm_103 base target (no tcgen05 available through harness PTX):
// encoder GEMM via mma.sync.m16n8k16 f16/f32, fused streaming top-32,
// margin-classified exact (fp64-rescued) selection, sparse decode.
// ============================================================================

static constexpr int SM_A    = 0;          // 128 x 264 f16, row stride 528B
static constexpr int SM_B    = 67584;      // 2 bufs x (64 x 264 f16 = 33792B)
static constexpr int SM_ACC  = 135168;     // 128 x 68 f32
static constexpr int SM_BENC = 169984;     // 4096 f32
static constexpr int SMEM_SZ = 186368;
static constexpr float MARG2 = 8e-3f;      // 2 * selection margin

__device__ __half g_Whi[8192 * 256];                // 4 MB fp16 W_enc
__device__ unsigned long long g_topp[8192 * 64];    // packed candidates

__device__ __forceinline__ uint32_t smem_u32(const void* p) {
    uint32_t a;
    asm("{ .reg .u64 t; cvta.to.shared.u64 t, %1; cvt.u32.u64 %0, t; }" : "=r"(a) : "l"(p));
    return a;
}
#define CPASYNC16(dst, src) \
    asm volatile("cp.async.cg.shared.global [%0], [%1], 16;" :: "r"(dst), "l"(src) : "memory")
#define CPCOMMIT() asm volatile("cp.async.commit_group;" ::: "memory")
#define CPWAIT1()  asm volatile("cp.async.wait_group 1;" ::: "memory")
#define CPWAIT0()  asm volatile("cp.async.wait_group 0;" ::: "memory")

#define MMA16816(d, a0, a1, a2, a3, b0, b1) \
    asm volatile("mma.sync.aligned.m16n8k16.row.col.f32.f16.f16.f32 " \
        "{%0,%1,%2,%3}, {%4,%5,%6,%7}, {%8,%9}, {%0,%1,%2,%3};" \
        : "+f"((d)[0]), "+f"((d)[1]), "+f"((d)[2]), "+f"((d)[3]) \
        : "r"(a0), "r"(a1), "r"(a2), "r"(a3), "r"(b0), "r"(b1))

// ============================================================================
__global__ void __launch_bounds__(1024) prep_w(const float* __restrict__ W) {
    int i = blockIdx.x * blockDim.x + threadIdx.x;   // grid exactly 2M
    g_Whi[i] = __float2half_rn(W[i]);
}

// ============================================================================
// grid (64 M-tiles, 2 H-halves), 256 threads (8 warps)
// ============================================================================
__device__ __forceinline__ void b_issue(uint32_t sb, const __half* src0,
                                        uint32_t dst0, int tid) {
    #pragma unroll
    for (int it = 0; it < 8; it++) {
        int q = tid + it * 256, r = q >> 5, seg = q & 31;
        CPASYNC16(dst0 + r * 528 + seg * 16, src0 + r * 256 + seg * 8);
    }
    CPCOMMIT();
}

__global__ void __launch_bounds__(256, 1)
encode_topk(const float* __restrict__ x, const float* __restrict__ b_enc,
            const float* __restrict__ b_dec) {
    extern __shared__ char smp[];
    const uint32_t sb = smem_u32(smp);
    const int tid = threadIdx.x;
    const int half = blockIdx.y, mrow0 = blockIdx.x * 128;

    // ---- prologue: A tile (x - b_dec) -> f16 padded smem; b_enc half copy ----
    {
        const float4* x4 = reinterpret_cast<const float4*>(x);
        const float4* bd4 = reinterpret_cast<const float4*>(b_dec);
        #pragma unroll 4
        for (int it = 0; it < 32; it++) {
            int u = tid + it * 256, r = u >> 6, c4 = u & 63;
            float4 v = x4[(size_t)(mrow0 + r) * 64 + c4];
            float4 bd = bd4[c4];
            __half2 h0 = __floats2half2_rn(v.x - bd.x, v.y - bd.y);
            __half2 h1 = __floats2half2_rn(v.z - bd.z, v.w - bd.w);
            uint2 s;
            s.x = *reinterpret_cast<uint32_t*>(&h0);
            s.y = *reinterpret_cast<uint32_t*>(&h1);
            *reinterpret_cast<uint2*>(smp + SM_A + r * 528 + c4 * 8) = s;
        }
        float* bf = reinterpret_cast<float*>(smp + SM_BENC);
        #pragma unroll
        for (int it = 0; it < 16; it++)
            bf[tid + it * 256] = b_enc[half * 4096 + tid + it * 256];
    }
    // prefetch B chunk 0
    b_issue(sb, g_Whi + (size_t)(half * 4096) * 256, sb + SM_B, tid);
    __syncthreads();   // A tile visible

    const int lane = tid & 31, w = tid >> 5;
    const int g = lane >> 2, t = lane & 3;
    const int mw = w * 16;
    float* accf = reinterpret_cast<float*>(smp + SM_ACC);
    const float* bf = reinterpret_cast<const float*>(smp + SM_BENC);

    unsigned long long L[32];
    #pragma unroll
    for (int j = 0; j < 32; j++) L[j] = 0ull;
    unsigned long long pmin = 0ull;
    int amin = 0;

    for (int c = 0; c < 64; c++) {
        if (c + 1 < 64)
            b_issue(sb, g_Whi + (size_t)(half * 4096 + (c + 1) * 64) * 256,
                    sb + SM_B + ((c + 1) & 1) * 33792, tid);
        if (c + 1 < 64) CPWAIT1(); else CPWAIT0();
        __syncthreads();   // B[c] ready, acc[c-1] consumed

        // ---- MMA: warp w computes rows mw..mw+15 x cols 0..63 ----
        const char* Bb = smp + SM_B + (c & 1) * 33792;
        float acc[8][4];
        #pragma unroll
        for (int nt = 0; nt < 8; nt++)
            { acc[nt][0] = 0.f; acc[nt][1] = 0.f; acc[nt][2] = 0.f; acc[nt][3] = 0.f; }
        #pragma unroll
        for (int kk = 0; kk < 16; kk++) {
            const char* Ar = smp + SM_A + (mw + g) * 528 + kk * 32 + 4 * t;
            uint32_t a0 = *reinterpret_cast<const uint32_t*>(Ar);
            uint32_t a1 = *reinterpret_cast<const uint32_t*>(Ar + 8 * 528);
            uint32_t a2 = *reinterpret_cast<const uint32_t*>(Ar + 16);
            uint32_t a3 = *reinterpret_cast<const uint32_t*>(Ar + 8 * 528 + 16);
            #pragma unroll
            for (int nt = 0; nt < 8; nt++) {
                const char* Br = Bb + (nt * 8 + g) * 528 + kk * 32 + 4 * t;
                uint32_t b0 = *reinterpret_cast<const uint32_t*>(Br);
                uint32_t b1 = *reinterpret_cast<const uint32_t*>(Br + 16);
                MMA16816(acc[nt], a0, a1, a2, a3, b0, b1);
            }
        }
        // ---- write accumulators to smem (conflict-free float2) ----
        #pragma unroll
        for (int nt = 0; nt < 8; nt++) {
            int col = nt * 8 + 2 * t;
            float2 lo; lo.x = acc[nt][0]; lo.y = acc[nt][1];
            float2 hi; hi.x = acc[nt][2]; hi.y = acc[nt][3];
            *reinterpret_cast<float2*>(accf + (mw + g) * 68 + col) = lo;
            *reinterpret_cast<float2*>(accf + (mw + g + 8) * 68 + col) = hi;
        }
        __syncthreads();

        // ---- streaming top-32 (one thread per row) ----
        if (tid < 128) {
            const float* ar = accf + tid * 68;
            const float* be = bf + c * 64;
            const int hbase = half * 4096 + c * 64;
            #pragma unroll 4
            for (int n = 0; n < 64; n++) {
                float v = fmaxf(ar[n] + be[n], 0.0f);
                unsigned long long p =
                    ((unsigned long long)__float_as_uint(v) << 32) |
                    (unsigned)(8191 - (hbase + n));
                if (p > pmin) {
                    #pragma unroll
                    for (int j = 0; j < 32; j++) if (j == amin) L[j] = p;
                    pmin = L[0]; amin = 0;
                    #pragma unroll
                    for (int j = 1; j < 32; j++)
                        if (L[j] < pmin) { pmin = L[j]; amin = j; }
                }
            }
        }
    }
    if (tid < 128) {
        const size_t base = (size_t)(mrow0 + tid) * 64 + half * 32;
        #pragma unroll 1
        for (int s = 0; s < 32; s++) g_topp[base + s] = L[s];
    }
}

// ============================================================================
// grid 8192, block 256: classify candidates, fp64 rescue ambiguous, exact
// select, sparse decode
// ============================================================================
__global__ void __launch_bounds__(256)
decode(const float* __restrict__ x, const float* __restrict__ W_enc,
       const float* __restrict__ b_enc, const float* __restrict__ W_dec,
       const float* __restrict__ b_dec, float* __restrict__ out) {
    __shared__ float sx[256], sa[64], selv[32];
    __shared__ int si[64], cls[64], seli[32];
    __shared__ double se[64];
    const int row = blockIdx.x, t = threadIdx.x;

    sx[t] = x[(size_t)row * 256 + t] - b_dec[t];
    if (t < 64) {
        unsigned long long p = g_topp[(size_t)row * 64 + t];
        sa[t] = __uint_as_float((uint32_t)(p >> 32));
        si[t] = 8191 - (int)(p & 0xFFFFFFFFu);
    }
    __syncthreads();
    if (t < 64) {
        float at = sa[t];
        int pos = 0, cert = 0;
        #pragma unroll 1
        for (int j = 0; j < 64; j++) {
            if (j == t) continue;
            pos  += (sa[j] >= at - MARG2);
            cert += (sa[j] >  at + MARG2);
        }
        cls[t] = (pos <= 31) ? 2 : (cert >= 32 ? 0 : 1);
    }
    __syncthreads();
    if (t < 64 && cls[t] == 1) {           // fp64 exact rescue (rare)
        const float* wr = W_enc + (size_t)si[t] * 256;
        double s0 = 0, s1 = 0, s2 = 0, s3 = 0;
        #pragma unroll 1
        for (int d = 0; d < 256; d += 4) {
            s0 += (double)sx[d]     * (double)wr[d];
            s1 += (double)sx[d + 1] * (double)wr[d + 1];
            s2 += (double)sx[d + 2] * (double)wr[d + 2];
            s3 += (double)sx[d + 3] * (double)wr[d + 3];
        }
        double e = s0 + s1 + s2 + s3 + (double)b_enc[si[t]];
        se[t] = e > 0.0 ? e : 0.0;
    }
    __syncthreads();
    if (t == 0) {
        int ns = 0;
        bool taken[64];
        #pragma unroll 1
        for (int j = 0; j < 64; j++) {
            taken[j] = false;
            if (cls[j] == 2 && ns < 32) { seli[ns] = si[j]; selv[ns] = sa[j]; ns++; }
        }
        while (ns < 32) {
            int best = -1, bi = 1 << 30;
            double bv = -1.0;
            #pragma unroll 1
            for (int j = 0; j < 64; j++) {
                if (cls[j] == 1 && !taken[j]) {
                    if (se[j] > bv || (se[j] == bv && si[j] < bi)) {
                        best = j; bv = se[j]; bi = si[j];
                    }
                }
            }
            if (best < 0) { seli[ns] = 0; selv[ns] = 0.0f; ns++; continue; }
            taken[best] = true;
            seli[ns] = si[best]; selv[ns] = (float)se[best]; ns++;
        }
    }
    __syncthreads();
    float acc = b_dec[t];
    #pragma unroll 8
    for (int k = 0; k < 32; k++)
        acc = fmaf(selv[k], W_dec[(size_t)seli[k] * 256 + t], acc);
    out[(size_t)row * 256 + t] = acc;
}

// ============================================================================
extern "C" void kernel_launch(void* const* d_in, const int* in_sizes, int n_in,
                              void* d_out, int out_size) {
    const float* x     = (const float*)d_in[0];
    const float* W_enc = (const float*)d_in[1];
    const float* b_enc = (const float*)d_in[2];
    const float* W_dec = (const float*)d_in[3];
    const float* b_dec = (const float*)d_in[4];
    float* out = (float*)d_out;

    cudaFuncSetAttribute(encode_topk, cudaFuncAttributeMaxDynamicSharedMemorySize, SMEM_SZ);
    prep_w<<<2048, 1024>>>(W_enc);
    encode_topk<<<dim3(64, 2), 256, SMEM_SZ>>>(x, b_enc, b_dec);
    decode<<<8192, 256>>>(x, W_enc, b_enc, W_dec, b_dec, out);
}

// round 9
// speedup vs baseline: 1.1804x; 1.1804x over previous
#include <cuda_runtime.h>
#include <cstdint>

// ============================================================================
// SAE forward, sm_103 base target (no tcgen05, no HMMA fast path => SIMT):
// encoder GEMM in packed fp32 (fma.rn.f32x2), fused streaming top-32,
// margin-classified exact selection (fp64 rescue, ~never fires), sparse decode.
// ============================================================================

static constexpr int SM_AT  = 0;                     // A^T: 256 k x (132 f32) = 135168 B
static constexpr int SM_B   = 135168;                // 2 bufs x (32 rows x 1040 B) = 66560
static constexpr int SM_ACC = 135168 + 66560;        // 128 x 33 f32 = 16896
static constexpr int SMEM_SZ = SM_ACC + 16896;       // 218624
static constexpr float MARG2 = 2e-4f;                // 2 * selection margin (fp32-exact GEMM)

__device__ unsigned long long g_topp[8192 * 64];     // packed candidates

__device__ __forceinline__ uint32_t smem_u32(const void* p) {
    uint32_t a;
    asm("{ .reg .u64 t; cvta.to.shared.u64 t, %1; cvt.u32.u64 %0, t; }" : "=r"(a) : "l"(p));
    return a;
}
#define CPASYNC16(dst, src) \
    asm volatile("cp.async.cg.shared.global [%0], [%1], 16;" :: "r"(dst), "l"(src) : "memory")
#define CPCOMMIT() asm volatile("cp.async.commit_group;" ::: "memory")
#define CPWAIT1()  asm volatile("cp.async.wait_group 1;" ::: "memory")
#define CPWAIT0()  asm volatile("cp.async.wait_group 0;" ::: "memory")

#define FMA2(d, a, b) \
    asm volatile("fma.rn.f32x2 %0, %1, %2, %0;" : "+l"(d) : "l"(a), "l"(b))
#define PACK2(d, x, y) \
    asm volatile("mov.b64 %0, {%1, %2};" : "=l"(d) : "f"(x), "f"(y))
#define UNPACK2(x, y, d) \
    asm volatile("mov.b64 {%0, %1}, %2;" : "=f"(x), "=f"(y) : "l"(d))

// ============================================================================
// encode: grid (64 M-tiles, 2 H-halves), 256 threads.
// Thread tile: rows {4*rgA .. 4*rgA+3} (contiguous), cols {cg, cg+8, cg+16, cg+24}.
// ============================================================================
__global__ void __launch_bounds__(256, 1)
encode_topk(const float* __restrict__ x, const float* __restrict__ W_enc,
            const float* __restrict__ b_enc, const float* __restrict__ b_dec) {
    extern __shared__ char smp[];
    const uint32_t sb = smem_u32(smp);
    const int tid = threadIdx.x;
    const int half = blockIdx.y, mrow0 = blockIdx.x * 128;
    const int hb0 = half * 4096;

    // ---- prologue: A^T[k][row] = x[row][k] - b_dec[k] (fp32, stride 132 f32) ----
    {
        const float4* x4 = reinterpret_cast<const float4*>(x);
        const float4* bd4 = reinterpret_cast<const float4*>(b_dec);
        #pragma unroll 4
        for (int it = 0; it < 32; it++) {
            int u = tid + it * 256, r = u >> 6, c4 = u & 63;
            float4 v = x4[(size_t)(mrow0 + r) * 64 + c4];
            float4 bd = bd4[c4];
            float* at = reinterpret_cast<float*>(smp + SM_AT) + (4 * c4) * 132 + r;
            at[0]       = v.x - bd.x;
            at[132]     = v.y - bd.y;
            at[264]     = v.z - bd.z;
            at[396]     = v.w - bd.w;
        }
    }
    // prefetch B chunk 0 (32 W_enc rows x 1KB)
    {
        const float* s0 = W_enc + (size_t)hb0 * 256;
        #pragma unroll
        for (int it = 0; it < 8; it++) {
            int q = tid + it * 256, r = q >> 6, s = q & 63;
            CPASYNC16(sb + SM_B + r * 1040 + s * 16, s0 + r * 256 + s * 4);
        }
        CPCOMMIT();
    }
    __syncthreads();

    const int rgA = tid >> 3, cg = tid & 7;
    const char* At = smp + SM_AT + rgA * 16;
    float* accf = reinterpret_cast<float*>(smp + SM_ACC);

    unsigned long long L[32], pmin = 0ull;
    int amin = 0;

    for (int c = 0; c < 128; c++) {
        const int buf = c & 1;
        if (c + 1 < 128) {
            const float* s0 = W_enc + (size_t)(hb0 + (c + 1) * 32) * 256;
            uint32_t d0 = sb + SM_B + ((c + 1) & 1) * 33280;
            #pragma unroll
            for (int it = 0; it < 8; it++) {
                int q = tid + it * 256, r = q >> 6, s = q & 63;
                CPASYNC16(d0 + r * 1040 + s * 16, s0 + r * 256 + s * 4);
            }
            CPCOMMIT();
            CPWAIT1();
        } else {
            CPWAIT0();
        }
        __syncthreads();  // B[c] ready; acc/topk of previous chunk consumed

        // ---- GEMM microtile: 4 rows x 4 cols over K=256 ----
        const char* Bb = smp + SM_B + buf * 33280;
        const char* Bp0 = Bb + (cg     ) * 1040;
        const char* Bp1 = Bb + (cg +  8) * 1040;
        const char* Bp2 = Bb + (cg + 16) * 1040;
        const char* Bp3 = Bb + (cg + 24) * 1040;
        unsigned long long acc00 = 0, acc01 = 0, acc02 = 0, acc03 = 0;
        unsigned long long acc10 = 0, acc11 = 0, acc12 = 0, acc13 = 0;
        #pragma unroll 16
        for (int k = 0; k < 256; k++) {
            float4 a4 = *reinterpret_cast<const float4*>(At + k * 528);
            unsigned long long ap0, ap1;
            PACK2(ap0, a4.x, a4.y);
            PACK2(ap1, a4.z, a4.w);
            float b0 = *reinterpret_cast<const float*>(Bp0 + k * 4);
            float b1 = *reinterpret_cast<const float*>(Bp1 + k * 4);
            float b2 = *reinterpret_cast<const float*>(Bp2 + k * 4);
            float b3 = *reinterpret_cast<const float*>(Bp3 + k * 4);
            unsigned long long bb0, bb1, bb2, bb3;
            PACK2(bb0, b0, b0); PACK2(bb1, b1, b1);
            PACK2(bb2, b2, b2); PACK2(bb3, b3, b3);
            FMA2(acc00, ap0, bb0); FMA2(acc01, ap0, bb1);
            FMA2(acc02, ap0, bb2); FMA2(acc03, ap0, bb3);
            FMA2(acc10, ap1, bb0); FMA2(acc11, ap1, bb1);
            FMA2(acc12, ap1, bb2); FMA2(acc13, ap1, bb3);
        }
        // ---- stage accumulators to smem [row][col], stride 33 f32 ----
        {
            float v0, v1;
            float* r0 = accf + (4 * rgA + 0) * 33;
            float* r1 = accf + (4 * rgA + 1) * 33;
            float* r2 = accf + (4 * rgA + 2) * 33;
            float* r3 = accf + (4 * rgA + 3) * 33;
            UNPACK2(v0, v1, acc00); r0[cg] = v0;      r1[cg] = v1;
            UNPACK2(v0, v1, acc01); r0[cg + 8] = v0;  r1[cg + 8] = v1;
            UNPACK2(v0, v1, acc02); r0[cg + 16] = v0; r1[cg + 16] = v1;
            UNPACK2(v0, v1, acc03); r0[cg + 24] = v0; r1[cg + 24] = v1;
            UNPACK2(v0, v1, acc10); r2[cg] = v0;      r3[cg] = v1;
            UNPACK2(v0, v1, acc11); r2[cg + 8] = v0;  r3[cg + 8] = v1;
            UNPACK2(v0, v1, acc12); r2[cg + 16] = v0; r3[cg + 16] = v1;
            UNPACK2(v0, v1, acc13); r2[cg + 24] = v0; r3[cg + 24] = v1;
        }
        __syncthreads();

        // ---- streaming top-32 (thread per row, 32 new values) ----
        if (tid < 128) {
            const float* ar = accf + tid * 33;
            const int hbase = hb0 + c * 32;
            if (c == 0) {
                #pragma unroll
                for (int n = 0; n < 32; n++) {
                    float v = fmaxf(ar[n] + __ldg(b_enc + hbase + n), 0.0f);
                    L[n] = ((unsigned long long)__float_as_uint(v) << 32) |
                           (unsigned)(8191 - (hbase + n));
                }
                pmin = L[0]; amin = 0;
                #pragma unroll
                for (int j = 1; j < 32; j++)
                    if (L[j] < pmin) { pmin = L[j]; amin = j; }
            } else {
                #pragma unroll 4
                for (int n = 0; n < 32; n++) {
                    float v = fmaxf(ar[n] + __ldg(b_enc + hbase + n), 0.0f);
                    unsigned long long p =
                        ((unsigned long long)__float_as_uint(v) << 32) |
                        (unsigned)(8191 - (hbase + n));
                    if (p > pmin) {
                        #pragma unroll
                        for (int j = 0; j < 32; j++) if (j == amin) L[j] = p;
                        pmin = L[0]; amin = 0;
                        #pragma unroll
                        for (int j = 1; j < 32; j++)
                            if (L[j] < pmin) { pmin = L[j]; amin = j; }
                    }
                }
            }
        }
    }
    if (tid < 128) {
        const size_t base = (size_t)(mrow0 + tid) * 64 + half * 32;
        #pragma unroll 1
        for (int s = 0; s < 32; s++) g_topp[base + s] = L[s];
    }
}

// ============================================================================
// decode: grid 8192, block 256 — classify 64 candidates, fp64 rescue the
// (rare) ambiguous ones, exact select top-32, sparse gather decode.
// ============================================================================
__global__ void __launch_bounds__(256)
decode(const float* __restrict__ x, const float* __restrict__ W_enc,
       const float* __restrict__ b_enc, const float* __restrict__ W_dec,
       const float* __restrict__ b_dec, float* __restrict__ out) {
    __shared__ float sx[256], sa[64], selv[32];
    __shared__ int si[64], cls[64], seli[32];
    __shared__ double se[64];
    const int row = blockIdx.x, t = threadIdx.x;

    sx[t] = x[(size_t)row * 256 + t] - b_dec[t];
    if (t < 64) {
        unsigned long long p = g_topp[(size_t)row * 64 + t];
        sa[t] = __uint_as_float((uint32_t)(p >> 32));
        si[t] = 8191 - (int)(p & 0xFFFFFFFFu);
    }
    __syncthreads();
    if (t < 64) {
        float at = sa[t];
        int pos = 0, cert = 0;
        #pragma unroll 1
        for (int j = 0; j < 64; j++) {
            if (j == t) continue;
            pos  += (sa[j] >= at - MARG2);
            cert += (sa[j] >  at + MARG2);
        }
        cls[t] = (pos <= 31) ? 2 : (cert >= 32 ? 0 : 1);
    }
    __syncthreads();
    if (t < 64 && cls[t] == 1) {   // fp64 exact rescue (rare with fp32 GEMM)
        const float* wr = W_enc + (size_t)si[t] * 256;
        double s0 = 0, s1 = 0, s2 = 0, s3 = 0;
        #pragma unroll 1
        for (int d = 0; d < 256; d += 4) {
            s0 += (double)sx[d]     * (double)wr[d];
            s1 += (double)sx[d + 1] * (double)wr[d + 1];
            s2 += (double)sx[d + 2] * (double)wr[d + 2];
            s3 += (double)sx[d + 3] * (double)wr[d + 3];
        }
        double e = s0 + s1 + s2 + s3 + (double)b_enc[si[t]];
        se[t] = e > 0.0 ? e : 0.0;
    }
    __syncthreads();
    if (t == 0) {
        int ns = 0;
        bool taken[64];
        #pragma unroll 1
        for (int j = 0; j < 64; j++) {
            taken[j] = false;
            if (cls[j] == 2 && ns < 32) { seli[ns] = si[j]; selv[ns] = sa[j]; ns++; }
        }
        while (ns < 32) {
            int best = -1, bi = 1 << 30;
            double bv = -1.0;
            #pragma unroll 1
            for (int j = 0; j < 64; j++) {
                if (cls[j] == 1 && !taken[j]) {
                    if (se[j] > bv || (se[j] == bv && si[j] < bi)) {
                        best = j; bv = se[j]; bi = si[j];
                    }
                }
            }
            if (best < 0) { seli[ns] = 0; selv[ns] = 0.0f; ns++; continue; }
            taken[best] = true;
            seli[ns] = si[best]; selv[ns] = (float)se[best]; ns++;
        }
    }
    __syncthreads();
    float acc = b_dec[t];
    #pragma unroll 8
    for (int k = 0; k < 32; k++)
        acc = fmaf(selv[k], W_dec[(size_t)seli[k] * 256 + t], acc);
    out[(size_t)row * 256 + t] = acc;
}

// ============================================================================
extern "C" void kernel_launch(void* const* d_in, const int* in_sizes, int n_in,
                              void* d_out, int out_size) {
    const float* x     = (const float*)d_in[0];
    const float* W_enc = (const float*)d_in[1];
    const float* b_enc = (const float*)d_in[2];
    const float* W_dec = (const float*)d_in[3];
    const float* b_dec = (const float*)d_in[4];
    float* out = (float*)d_out;

    cudaFuncSetAttribute(encode_topk, cudaFuncAttributeMaxDynamicSharedMemorySize, SMEM_SZ);
    encode_topk<<<dim3(64, 2), 256, SMEM_SZ>>>(x, W_enc, b_enc, b_dec);
    decode<<<8192, 256>>>(x, W_enc, b_enc, W_dec, b_dec, out);
}

// round 10
// speedup vs baseline: 2.1962x; 1.8605x over previous
#include <cuda_runtime.h>
#include <cstdint>

// ============================================================================
// SAE forward, sm_103 base target (no tcgen05 via harness toolchain => SIMT):
// fp32 encoder GEMM with packed fma.rn.f32x2, fused streaming top-32,
// margin-classified exact selection (fp64 rescue), sparse decode.
// encode: 128 CTAs x 512 thr; A^T k-major resident; B 32-col chunks dbl-buf.
// ============================================================================

static constexpr int SM_AT  = 0;                       // A^T: 256 x 132 f32 = 135168 B
static constexpr int SM_B   = 135168;                  // 2 x (32 cols x 261 f32) = 66816 B
static constexpr int B_BUF  = 33408;
static constexpr int SM_ACC = 135168 + 66816;          // 128 x 34 f32 = 17408 B
static constexpr int SMEM_SZ = SM_ACC + 17408;         // 219392 B
static constexpr float MARG2 = 2e-4f;                  // 2 * selection margin

__device__ unsigned long long g_topp[8192 * 64];       // packed candidates

__device__ __forceinline__ uint32_t smem_u32(const void* p) {
    uint32_t a;
    asm("{ .reg .u64 t; cvta.to.shared.u64 t, %1; cvt.u32.u64 %0, t; }" : "=r"(a) : "l"(p));
    return a;
}
#define CPASYNC4(dst, src) \
    asm volatile("cp.async.ca.shared.global [%0], [%1], 4;" :: "r"(dst), "l"(src) : "memory")
#define CPCOMMIT() asm volatile("cp.async.commit_group;" ::: "memory")
#define CPWAIT1()  asm volatile("cp.async.wait_group 1;" ::: "memory")
#define CPWAIT0()  asm volatile("cp.async.wait_group 0;" ::: "memory")

// non-volatile: let ptxas schedule/pipeline these freely
#define FMA2(d, a, b) \
    asm("fma.rn.f32x2 %0, %1, %2, %0;" : "+l"(d) : "l"(a), "l"(b))
#define PACK2(d, x, y) \
    asm("mov.b64 %0, {%1, %2};" : "=l"(d) : "f"(x), "f"(y))
#define UNPACK2(x, y, d) \
    asm("mov.b64 {%0, %1}, %2;" : "=f"(x), "=f"(y) : "l"(d))

// ============================================================================
// encode: grid (64 M-tiles, 2 H-halves), 512 threads.
// rg = tid>>4 (rows 4rg..4rg+3), cg = tid&15 (cols cg, cg+16 of 32-col chunk).
// ============================================================================
__global__ void __launch_bounds__(512, 1)
encode_topk(const float* __restrict__ x, const float* __restrict__ W_enc,
            const float* __restrict__ b_enc, const float* __restrict__ b_dec) {
    extern __shared__ char smp[];
    const uint32_t sb = smem_u32(smp);
    const int tid = threadIdx.x;
    const int half = blockIdx.y, mrow0 = blockIdx.x * 128;
    const int hb0 = half * 4096;

    // ---- prologue: A^T[k][r] = x[mrow0+r][k] - b_dec[k]; stride 132 f32 ----
    // mapping: r lane-consecutive -> conflict-free STS (banks = r)
    {
        const float4* x4 = reinterpret_cast<const float4*>(x);
        const float4* bd4 = reinterpret_cast<const float4*>(b_dec);
        float* at = reinterpret_cast<float*>(smp + SM_AT);
        #pragma unroll
        for (int it = 0; it < 16; it++) {
            int u = tid + it * 512;          // 0..8191
            int r = u & 127, c4 = u >> 7;    // c4 = 0..63 (float4 col)
            float4 v = x4[(size_t)(mrow0 + r) * 64 + c4];
            float4 bd = bd4[c4];
            float* p = at + (4 * c4) * 132 + r;
            p[0]   = v.x - bd.x;
            p[132] = v.y - bd.y;
            p[264] = v.z - bd.z;
            p[396] = v.w - bd.w;
        }
    }
    // ---- prefetch B chunk 0: 32 W rows x 256 k, smem [col][k] stride 261 ----
    {
        const float* s0 = W_enc + (size_t)hb0 * 256;
        #pragma unroll
        for (int it = 0; it < 16; it++) {
            int q = tid + it * 512, col = q >> 8, k = q & 255;
            CPASYNC4(sb + SM_B + (uint32_t)(col * 261 + k) * 4, s0 + col * 256 + k);
        }
        CPCOMMIT();
    }

    const int rg = tid >> 4, cg = tid & 15;
    const char* At = smp + SM_AT + rg * 16;
    float* accf = reinterpret_cast<float*>(smp + SM_ACC);

    unsigned long long L[32], pmin = 0ull;
    int amin = 0;

    for (int c = 0; c < 128; c++) {
        const int buf = c & 1;
        if (c + 1 < 128) {
            const float* s0 = W_enc + (size_t)(hb0 + (c + 1) * 32) * 256;
            const uint32_t d0 = sb + SM_B + ((c + 1) & 1) * B_BUF;
            #pragma unroll
            for (int it = 0; it < 16; it++) {
                int q = tid + it * 512, col = q >> 8, k = q & 255;
                CPASYNC4(d0 + (uint32_t)(col * 261 + k) * 4, s0 + col * 256 + k);
            }
            CPCOMMIT();
            CPWAIT1();
        } else {
            CPWAIT0();
        }
        __syncthreads();   // B[c] visible; prev topk done before acc re-stage

        // ---- GEMM microtile 4 rows x 2 cols over K=256 ----
        const float* Bb = reinterpret_cast<const float*>(smp + SM_B + buf * B_BUF);
        const float* Bc0 = Bb + cg * 261;
        const float* Bc1 = Bb + (cg + 16) * 261;
        unsigned long long acc00 = 0, acc01 = 0, acc10 = 0, acc11 = 0;
        #pragma unroll 8
        for (int k = 0; k < 256; k++) {
            ulonglong2 a = *reinterpret_cast<const ulonglong2*>(At + k * 528);
            float b0 = Bc0[k], b1 = Bc1[k];
            unsigned long long bb0, bb1;
            PACK2(bb0, b0, b0);
            PACK2(bb1, b1, b1);
            FMA2(acc00, a.x, bb0);
            FMA2(acc01, a.x, bb1);
            FMA2(acc10, a.y, bb0);
            FMA2(acc11, a.y, bb1);
        }
        // ---- stage accumulators: acc[(row)][col], stride 34 ----
        {
            float v0, v1;
            float* r0 = accf + (4 * rg) * 34;
            UNPACK2(v0, v1, acc00); r0[cg] = v0;            r0[34 + cg] = v1;
            UNPACK2(v0, v1, acc01); r0[cg + 16] = v0;       r0[34 + cg + 16] = v1;
            UNPACK2(v0, v1, acc10); r0[68 + cg] = v0;       r0[102 + cg] = v1;
            UNPACK2(v0, v1, acc11); r0[68 + cg + 16] = v0;  r0[102 + cg + 16] = v1;
        }
        __syncthreads();

        // ---- streaming top-32 (thread per row, 32 new values) ----
        if (tid < 128) {
            const float* ar = accf + tid * 34;
            const int hbase = hb0 + c * 32;
            if (c == 0) {
                #pragma unroll
                for (int n = 0; n < 32; n++) {
                    float v = fmaxf(ar[n] + __ldg(b_enc + hbase + n), 0.0f);
                    L[n] = ((unsigned long long)__float_as_uint(v) << 32) |
                           (unsigned)(8191 - (hbase + n));
                }
                pmin = L[0]; amin = 0;
                #pragma unroll
                for (int j = 1; j < 32; j++)
                    if (L[j] < pmin) { pmin = L[j]; amin = j; }
            } else {
                #pragma unroll 4
                for (int n = 0; n < 32; n++) {
                    float v = fmaxf(ar[n] + __ldg(b_enc + hbase + n), 0.0f);
                    unsigned long long p =
                        ((unsigned long long)__float_as_uint(v) << 32) |
                        (unsigned)(8191 - (hbase + n));
                    if (p > pmin) {
                        #pragma unroll
                        for (int j = 0; j < 32; j++) if (j == amin) L[j] = p;
                        pmin = L[0]; amin = 0;
                        #pragma unroll
                        for (int j = 1; j < 32; j++)
                            if (L[j] < pmin) { pmin = L[j]; amin = j; }
                    }
                }
            }
        }
    }
    if (tid < 128) {
        const size_t base = (size_t)(mrow0 + tid) * 64 + half * 32;
        #pragma unroll 1
        for (int s = 0; s < 32; s++) g_topp[base + s] = L[s];
    }
}

// ============================================================================
// decode: grid 8192, block 256 — classify 64 candidates, fp64 rescue the
// (rare) ambiguous ones, exact select top-32, sparse gather decode.
// ============================================================================
__global__ void __launch_bounds__(256)
decode(const float* __restrict__ x, const float* __restrict__ W_enc,
       const float* __restrict__ b_enc, const float* __restrict__ W_dec,
       const float* __restrict__ b_dec, float* __restrict__ out) {
    __shared__ float sx[256], sa[64], selv[32];
    __shared__ int si[64], cls[64], seli[32];
    __shared__ double se[64];
    const int row = blockIdx.x, t = threadIdx.x;

    sx[t] = x[(size_t)row * 256 + t] - b_dec[t];
    if (t < 64) {
        unsigned long long p = g_topp[(size_t)row * 64 + t];
        sa[t] = __uint_as_float((uint32_t)(p >> 32));
        si[t] = 8191 - (int)(p & 0xFFFFFFFFu);
    }
    __syncthreads();
    if (t < 64) {
        float at = sa[t];
        int pos = 0, cert = 0;
        #pragma unroll 1
        for (int j = 0; j < 64; j++) {
            if (j == t) continue;
            pos  += (sa[j] >= at - MARG2);
            cert += (sa[j] >  at + MARG2);
        }
        cls[t] = (pos <= 31) ? 2 : (cert >= 32 ? 0 : 1);
    }
    __syncthreads();
    if (t < 64 && cls[t] == 1) {          // fp64 exact rescue (rare)
        const float* wr = W_enc + (size_t)si[t] * 256;
        double s0 = 0, s1 = 0, s2 = 0, s3 = 0;
        #pragma unroll 1
        for (int d = 0; d < 256; d += 4) {
            s0 += (double)sx[d]     * (double)wr[d];
            s1 += (double)sx[d + 1] * (double)wr[d + 1];
            s2 += (double)sx[d + 2] * (double)wr[d + 2];
            s3 += (double)sx[d + 3] * (double)wr[d + 3];
        }
        double e = s0 + s1 + s2 + s3 + (double)b_enc[si[t]];
        se[t] = e > 0.0 ? e : 0.0;
    }
    __syncthreads();
    if (t == 0) {
        int ns = 0;
        bool taken[64];
        #pragma unroll 1
        for (int j = 0; j < 64; j++) {
            taken[j] = false;
            if (cls[j] == 2 && ns < 32) { seli[ns] = si[j]; selv[ns] = sa[j]; ns++; }
        }
        while (ns < 32) {
            int best = -1, bi = 1 << 30;
            double bv = -1.0;
            #pragma unroll 1
            for (int j = 0; j < 64; j++) {
                if (cls[j] == 1 && !taken[j]) {
                    if (se[j] > bv || (se[j] == bv && si[j] < bi)) {
                        best = j; bv = se[j]; bi = si[j];
                    }
                }
            }
            if (best < 0) { seli[ns] = 0; selv[ns] = 0.0f; ns++; continue; }
            taken[best] = true;
            seli[ns] = si[best]; selv[ns] = (float)se[best]; ns++;
        }
    }
    __syncthreads();
    float acc = b_dec[t];
    #pragma unroll 8
    for (int k = 0; k < 32; k++)
        acc = fmaf(selv[k], W_dec[(size_t)seli[k] * 256 + t], acc);
    out[(size_t)row * 256 + t] = acc;
}

// ============================================================================
extern "C" void kernel_launch(void* const* d_in, const int* in_sizes, int n_in,
                              void* d_out, int out_size) {
    const float* x     = (const float*)d_in[0];
    const float* W_enc = (const float*)d_in[1];
    const float* b_enc = (const float*)d_in[2];
    const float* W_dec = (const float*)d_in[3];
    const float* b_dec = (const float*)d_in[4];
    float* out = (float*)d_out;

    cudaFuncSetAttribute(encode_topk, cudaFuncAttributeMaxDynamicSharedMemorySize, SMEM_SZ);
    encode_topk<<<dim3(64, 2), 512, SMEM_SZ>>>(x, W_enc, b_enc, b_dec);
    decode<<<8192, 256>>>(x, W_enc, b_enc, W_dec, b_dec, out);
}